// round 2
// baseline (speedup 1.0000x reference)
#include <cuda_runtime.h>
#include <math.h>

// ---------------------------------------------------------------------------
// CausalEdgeAttention — algebraically reduced:
//   out = edge_attr + h1 @ Meff2 + c2
//   h1  = relu( (nf[src]+nf[tgt]) @ (0.5*n_W1) + n_b1 )        [E,256]
//   Meff2 = 0.5 * diag(scale) * (n_W2 @ Wv @ Wo @ Wp)           [256,8]
//   c2    = 0.5 * (c + shift @ M),  c = ((b2@Wv+bv)@Wo+bo)@Wp+bp
//   scale = gamma*rsqrt(var+eps), shift = beta - mu*scale  (BN stats of h1)
// Edge encoder in the reference is dead code (unused output) -> skipped.
// ---------------------------------------------------------------------------

#define HDIM 256
#define DDIM 8
#define NBLKA 1024

typedef unsigned long long u64;

__device__ __forceinline__ u64 pk(float lo, float hi) {
    u64 r; asm("mov.b64 %0,{%1,%2};" : "=l"(r) : "f"(lo), "f"(hi)); return r;
}
__device__ __forceinline__ void upk(u64 v, float& lo, float& hi) {
    asm("mov.b64 {%0,%1},%2;" : "=f"(lo), "=f"(hi) : "l"(v));
}
__device__ __forceinline__ u64 f2mul(u64 a, u64 b) {
    u64 d; asm("mul.rn.f32x2 %0,%1,%2;" : "=l"(d) : "l"(a), "l"(b)); return d;
}
__device__ __forceinline__ u64 f2fma(u64 a, u64 b, u64 c) {
    u64 d; asm("fma.rn.f32x2 %0,%1,%2,%3;" : "=l"(d) : "l"(a), "l"(b), "l"(c)); return d;
}

// ------------------------- scratch (device globals; no allocs) -------------
__device__ float g_R1[HDIM * DDIM];     // Wo @ Wp
__device__ float g_R2[HDIM * DDIM];     // Wv @ R1
__device__ float g_M [HDIM * DDIM];     // n_W2 @ R2
__device__ float g_c [DDIM];            // bias chain
__device__ float g_psum[NBLKA * HDIM];  // BN partial sums
__device__ float g_psq [NBLKA * HDIM];  // BN partial sum-of-squares
__device__ u64   g_Meff[HDIM * 4];      // packed (d-pairs) 0.5*scale[h]*M[h][:]
__device__ float g_c2[DDIM];

// ------------------------- fold kernels: out[H,8] = A[H,H] @ B[H,8] --------
__global__ void __launch_bounds__(256) fold1_kernel(const float* __restrict__ A,
                                                    const float* __restrict__ B) {
    __shared__ float Bs[HDIM * DDIM];
    int t = threadIdx.x;
    for (int i = t; i < HDIM * DDIM; i += 256) Bs[i] = B[i];
    __syncthreads();
    int g = blockIdx.x * 256 + t;     // 8 blocks x 256 = 2048 threads
    int h = g >> 3, d = g & 7;
    const float* Ar = A + h * HDIM;
    float acc = 0.f;
#pragma unroll 8
    for (int k = 0; k < HDIM; k++) acc = fmaf(__ldg(Ar + k), Bs[k * 8 + d], acc);
    g_R1[h * 8 + d] = acc;
}
__global__ void __launch_bounds__(256) fold2_kernel(const float* __restrict__ A) {
    __shared__ float Bs[HDIM * DDIM];
    int t = threadIdx.x;
    for (int i = t; i < HDIM * DDIM; i += 256) Bs[i] = g_R1[i];
    __syncthreads();
    int g = blockIdx.x * 256 + t;
    int h = g >> 3, d = g & 7;
    const float* Ar = A + h * HDIM;
    float acc = 0.f;
#pragma unroll 8
    for (int k = 0; k < HDIM; k++) acc = fmaf(__ldg(Ar + k), Bs[k * 8 + d], acc);
    g_R2[h * 8 + d] = acc;
}
__global__ void __launch_bounds__(256) fold3_kernel(const float* __restrict__ A) {
    __shared__ float Bs[HDIM * DDIM];
    int t = threadIdx.x;
    for (int i = t; i < HDIM * DDIM; i += 256) Bs[i] = g_R2[i];
    __syncthreads();
    int g = blockIdx.x * 256 + t;
    int h = g >> 3, d = g & 7;
    const float* Ar = A + h * HDIM;
    float acc = 0.f;
#pragma unroll 8
    for (int k = 0; k < HDIM; k++) acc = fmaf(__ldg(Ar + k), Bs[k * 8 + d], acc);
    g_M[h * 8 + d] = acc;
}

// ------------------------- bias chain: c = ((b2@Wv+bv)@Wo+bo)@Wp+bp --------
__global__ void __launch_bounds__(256) bias_kernel(const float* __restrict__ b2,
                                                   const float* __restrict__ Wv,
                                                   const float* __restrict__ bv,
                                                   const float* __restrict__ Wo,
                                                   const float* __restrict__ bo,
                                                   const float* __restrict__ Wp,
                                                   const float* __restrict__ bp) {
    __shared__ float v1[HDIM], v2[HDIM];
    int t = threadIdx.x;
    float acc = bv[t];
#pragma unroll 8
    for (int k = 0; k < HDIM; k++) acc = fmaf(__ldg(b2 + k), __ldg(Wv + k * HDIM + t), acc);
    v1[t] = acc;
    __syncthreads();
    acc = bo[t];
#pragma unroll 8
    for (int k = 0; k < HDIM; k++) acc = fmaf(v1[k], __ldg(Wo + k * HDIM + t), acc);
    v2[t] = acc;
    __syncthreads();
    if (t < DDIM) {
        float c = bp[t];
#pragma unroll 8
        for (int k = 0; k < HDIM; k++) c = fmaf(v2[k], __ldg(Wp + k * DDIM + t), c);
        g_c[t] = c;
    }
}

// ------------------------- pass A: BN statistics of h1 ---------------------
// thread = channel; W1 column resident in packed registers; nc staged in smem.
__global__ void __launch_bounds__(256) stats_kernel(const float* __restrict__ nf,
                                                    const int* __restrict__ ei0,
                                                    const int* __restrict__ ei1,
                                                    const float* __restrict__ W1,
                                                    const float* __restrict__ b1,
                                                    int E) {
    __shared__ u64 ncs[256 * 4];
    int t = threadIdx.x;
    u64 w0 = pk(0.5f * W1[0 * HDIM + t], 0.5f * W1[1 * HDIM + t]);
    u64 w1 = pk(0.5f * W1[2 * HDIM + t], 0.5f * W1[3 * HDIM + t]);
    u64 w2 = pk(0.5f * W1[4 * HDIM + t], 0.5f * W1[5 * HDIM + t]);
    u64 w3 = pk(0.5f * W1[6 * HDIM + t], 0.5f * W1[7 * HDIM + t]);
    float b1h = b1[t];
    float sum = 0.f, sq = 0.f;
    const float4* nfp = (const float4*)nf;

    for (int base = blockIdx.x * 256; base < E; base += gridDim.x * 256) {
        int nval = min(256, E - base);
        __syncthreads();
        if (t < nval) {
            int e = base + t;
            int s = __ldg(ei0 + e), g = __ldg(ei1 + e);
            float4 a0 = __ldg(nfp + 2 * s), a1 = __ldg(nfp + 2 * s + 1);
            float4 c0 = __ldg(nfp + 2 * g), c1 = __ldg(nfp + 2 * g + 1);
            ncs[t * 4 + 0] = pk(a0.x + c0.x, a0.y + c0.y);
            ncs[t * 4 + 1] = pk(a0.z + c0.z, a0.w + c0.w);
            ncs[t * 4 + 2] = pk(a1.x + c1.x, a1.y + c1.y);
            ncs[t * 4 + 3] = pk(a1.z + c1.z, a1.w + c1.w);
        }
        __syncthreads();
#pragma unroll 4
        for (int j = 0; j < nval; j++) {
            u64 s_ = f2mul(ncs[j * 4 + 0], w0);
            s_ = f2fma(ncs[j * 4 + 1], w1, s_);
            s_ = f2fma(ncs[j * 4 + 2], w2, s_);
            s_ = f2fma(ncs[j * 4 + 3], w3, s_);
            float lo, hi; upk(s_, lo, hi);
            float h1 = fmaxf(lo + hi + b1h, 0.f);
            sum += h1;
            sq = fmaf(h1, h1, sq);
        }
    }
    g_psum[blockIdx.x * HDIM + t] = sum;
    g_psq [blockIdx.x * HDIM + t] = sq;
}

// ------------------------- reduce + finalize -------------------------------
__global__ void __launch_bounds__(256) finalize_kernel(const float* __restrict__ gamma,
                                                       const float* __restrict__ beta,
                                                       int E) {
    __shared__ float red[256];
    int t = threadIdx.x;
    float s = 0.f, q = 0.f;
    for (int b = 0; b < NBLKA; b++) {
        s += g_psum[b * HDIM + t];
        q += g_psq [b * HDIM + t];
    }
    float invE = 1.0f / (float)E;
    float mu = s * invE;
    float var = fmaxf(q * invE - mu * mu, 0.f);
    float scl = gamma[t] * rsqrtf(var + 1e-5f);
    float shf = beta[t] - mu * scl;

    float m[DDIM];
#pragma unroll
    for (int d = 0; d < DDIM; d++) m[d] = g_M[t * DDIM + d];
#pragma unroll
    for (int p = 0; p < 4; p++)
        g_Meff[t * 4 + p] = pk(0.5f * scl * m[2 * p], 0.5f * scl * m[2 * p + 1]);

#pragma unroll
    for (int d = 0; d < DDIM; d++) {
        red[t] = shf * m[d];
        __syncthreads();
        for (int step = 128; step > 0; step >>= 1) {
            if (t < step) red[t] += red[t + step];
            __syncthreads();
        }
        if (t == 0) g_c2[d] = 0.5f * (g_c[d] + red[0]);
        __syncthreads();
    }
}

// ------------------------- pass B: main (2 edges / thread) -----------------
__global__ void __launch_bounds__(256) main_kernel(const float* __restrict__ edge_attr,
                                                   const float* __restrict__ nf,
                                                   const int* __restrict__ ei0,
                                                   const int* __restrict__ ei1,
                                                   const float* __restrict__ W1,
                                                   const float* __restrict__ b1,
                                                   float* __restrict__ out,
                                                   int E) {
    __shared__ u64 wp[HDIM * 4];
    __shared__ u64 mp[HDIM * 4];
    __shared__ float b1s[HDIM];
    int t = threadIdx.x;
    for (int idx = t; idx < HDIM * 4; idx += 256) {
        int h = idx >> 2, p = idx & 3;
        wp[idx] = pk(0.5f * W1[(2 * p) * HDIM + h], 0.5f * W1[(2 * p + 1) * HDIM + h]);
        mp[idx] = g_Meff[idx];
    }
    b1s[t] = b1[t];
    __syncthreads();

    int e0 = (blockIdx.x * 256 + t) * 2;
    if (e0 >= E) return;
    bool v1 = (e0 + 1) < E;
    int eB = v1 ? e0 + 1 : e0;

    float cz0 = g_c2[0], cz1 = g_c2[1], cz2 = g_c2[2], cz3 = g_c2[3];
    float cz4 = g_c2[4], cz5 = g_c2[5], cz6 = g_c2[6], cz7 = g_c2[7];

    int sA = __ldg(ei0 + e0), gA = __ldg(ei1 + e0);
    int sB = __ldg(ei0 + eB), gB = __ldg(ei1 + eB);
    const float4* nfp = (const float4*)nf;
    float4 a0 = __ldg(nfp + 2 * sA), a1 = __ldg(nfp + 2 * sA + 1);
    float4 c0 = __ldg(nfp + 2 * gA), c1 = __ldg(nfp + 2 * gA + 1);
    float4 p0 = __ldg(nfp + 2 * sB), p1 = __ldg(nfp + 2 * sB + 1);
    float4 q0 = __ldg(nfp + 2 * gB), q1 = __ldg(nfp + 2 * gB + 1);

    u64 nA0 = pk(a0.x + c0.x, a0.y + c0.y), nA1 = pk(a0.z + c0.z, a0.w + c0.w);
    u64 nA2 = pk(a1.x + c1.x, a1.y + c1.y), nA3 = pk(a1.z + c1.z, a1.w + c1.w);
    u64 nB0 = pk(p0.x + q0.x, p0.y + q0.y), nB1 = pk(p0.z + q0.z, p0.w + q0.w);
    u64 nB2 = pk(p1.x + q1.x, p1.y + q1.y), nB3 = pk(p1.z + q1.z, p1.w + q1.w);

    u64 aA0 = 0, aA1 = 0, aA2 = 0, aA3 = 0;
    u64 aB0 = 0, aB1 = 0, aB2 = 0, aB3 = 0;

#pragma unroll 4
    for (int h = 0; h < HDIM; h++) {
        u64 w0 = wp[h * 4 + 0], w1 = wp[h * 4 + 1], w2 = wp[h * 4 + 2], w3 = wp[h * 4 + 3];
        u64 m0 = mp[h * 4 + 0], m1 = mp[h * 4 + 1], m2 = mp[h * 4 + 2], m3 = mp[h * 4 + 3];
        float bb = b1s[h];

        u64 s_ = f2mul(nA0, w0);
        s_ = f2fma(nA1, w1, s_); s_ = f2fma(nA2, w2, s_); s_ = f2fma(nA3, w3, s_);
        float lo, hi; upk(s_, lo, hi);
        float h1 = fmaxf(lo + hi + bb, 0.f);
        u64 hh = pk(h1, h1);
        aA0 = f2fma(hh, m0, aA0); aA1 = f2fma(hh, m1, aA1);
        aA2 = f2fma(hh, m2, aA2); aA3 = f2fma(hh, m3, aA3);

        u64 s2 = f2mul(nB0, w0);
        s2 = f2fma(nB1, w1, s2); s2 = f2fma(nB2, w2, s2); s2 = f2fma(nB3, w3, s2);
        float lo2, hi2; upk(s2, lo2, hi2);
        float h2 = fmaxf(lo2 + hi2 + bb, 0.f);
        u64 h2h = pk(h2, h2);
        aB0 = f2fma(h2h, m0, aB0); aB1 = f2fma(h2h, m1, aB1);
        aB2 = f2fma(h2h, m2, aB2); aB3 = f2fma(h2h, m3, aB3);
    }

    const float4* eap = (const float4*)edge_attr;
    float4* outp = (float4*)out;
    {
        float4 e00 = __ldg(eap + e0 * 2), e01 = __ldg(eap + e0 * 2 + 1);
        float x0, x1, x2, x3, x4, x5, x6, x7;
        upk(aA0, x0, x1); upk(aA1, x2, x3); upk(aA2, x4, x5); upk(aA3, x6, x7);
        float4 o0, o1;
        o0.x = e00.x + x0 + cz0; o0.y = e00.y + x1 + cz1;
        o0.z = e00.z + x2 + cz2; o0.w = e00.w + x3 + cz3;
        o1.x = e01.x + x4 + cz4; o1.y = e01.y + x5 + cz5;
        o1.z = e01.z + x6 + cz6; o1.w = e01.w + x7 + cz7;
        outp[e0 * 2] = o0; outp[e0 * 2 + 1] = o1;
    }
    if (v1) {
        int e1 = e0 + 1;
        float4 e10 = __ldg(eap + e1 * 2), e11 = __ldg(eap + e1 * 2 + 1);
        float x0, x1, x2, x3, x4, x5, x6, x7;
        upk(aB0, x0, x1); upk(aB1, x2, x3); upk(aB2, x4, x5); upk(aB3, x6, x7);
        float4 o0, o1;
        o0.x = e10.x + x0 + cz0; o0.y = e10.y + x1 + cz1;
        o0.z = e10.z + x2 + cz2; o0.w = e10.w + x3 + cz3;
        o1.x = e11.x + x4 + cz4; o1.y = e11.y + x5 + cz5;
        o1.z = e11.z + x6 + cz6; o1.w = e11.w + x7 + cz7;
        outp[e1 * 2] = o0; outp[e1 * 2 + 1] = o1;
    }
}

// ------------------------- launch ------------------------------------------
extern "C" void kernel_launch(void* const* d_in, const int* in_sizes, int n_in,
                              void* d_out, int out_size) {
    const float* edge_attr = (const float*)d_in[0];
    const float* nf        = (const float*)d_in[1];
    const int*   ei        = (const int*)  d_in[2];
    // d_in[3..8] = edge encoder params: dead code in the reference, unused.
    const float* nW1   = (const float*)d_in[9];
    const float* nb1   = (const float*)d_in[10];
    const float* ngam  = (const float*)d_in[11];
    const float* nbet  = (const float*)d_in[12];
    const float* nW2   = (const float*)d_in[13];
    const float* nb2   = (const float*)d_in[14];
    const float* Wv    = (const float*)d_in[15];
    const float* bv    = (const float*)d_in[16];
    const float* Wo    = (const float*)d_in[17];
    const float* bo    = (const float*)d_in[18];
    const float* Wp    = (const float*)d_in[19];
    const float* bp    = (const float*)d_in[20];
    (void)n_in; (void)out_size;

    int E = in_sizes[0] / DDIM;
    const int* ei0 = ei;
    const int* ei1 = ei + E;
    float* out = (float*)d_out;

    // weight folding (independent of edge data, cheap)
    fold1_kernel<<<8, 256>>>(Wo, Wp);
    fold2_kernel<<<8, 256>>>(Wv);
    fold3_kernel<<<8, 256>>>(nW2);
    bias_kernel<<<1, 256>>>(nb2, Wv, bv, Wo, bo, Wp, bp);

    // BN statistics over h1
    stats_kernel<<<NBLKA, 256>>>(nf, ei0, ei1, nW1, nb1, E);
    finalize_kernel<<<1, 256>>>(ngam, nbet, E);

    // main fused pass
    int gridB = (E + 511) / 512;
    main_kernel<<<gridB, 256>>>(edge_attr, nf, ei0, ei1, nW1, nb1, out, E);
}

// round 4
// speedup vs baseline: 1.2737x; 1.2737x over previous
#include <cuda_runtime.h>
#include <math.h>

// ---------------------------------------------------------------------------
// CausalEdgeAttention — algebraically reduced:
//   out = edge_attr + h1 @ Meff2 + c2
//   h1  = relu( (nf[src]+nf[tgt]) @ (0.5*n_W1) + n_b1 )        [E,256]
//   Meff2 = 0.5 * diag(scale) * M,  M = n_W2 @ Wv @ Wo @ Wp    [256,8]
//   c2    = 0.5 * (b2@R2 + bv@R1 + bo@Wp + bp + shift@M)
//   scale = gamma*rsqrt(var+eps), shift = beta - mu*scale  (BN stats of h1)
// Edge encoder in the reference is dead code (unused output) -> skipped.
// ---------------------------------------------------------------------------

#define HDIM 256
#define DDIM 8
#define NBLKA 512

typedef unsigned long long u64;

__device__ __forceinline__ u64 pk(float lo, float hi) {
    u64 r; asm("mov.b64 %0,{%1,%2};" : "=l"(r) : "f"(lo), "f"(hi)); return r;
}
__device__ __forceinline__ void upk(u64 v, float& lo, float& hi) {
    asm("mov.b64 {%0,%1},%2;" : "=f"(lo), "=f"(hi) : "l"(v));
}
__device__ __forceinline__ u64 f2mul(u64 a, u64 b) {
    u64 d; asm("mul.rn.f32x2 %0,%1,%2;" : "=l"(d) : "l"(a), "l"(b)); return d;
}
__device__ __forceinline__ u64 f2fma(u64 a, u64 b, u64 c) {
    u64 d; asm("fma.rn.f32x2 %0,%1,%2,%3;" : "=l"(d) : "l"(a), "l"(b), "l"(c)); return d;
}

// ------------------------- scratch (device globals; no allocs) -------------
__device__ float  g_R1[HDIM * DDIM];     // Wo @ Wp
__device__ float  g_R2[HDIM * DDIM];     // Wv @ R1
__device__ float  g_M [HDIM * DDIM];     // n_W2 @ R2
__device__ float2 g_ps[NBLKA * HDIM];    // BN partials (sum, sumsq) interleaved
__device__ u64    g_Meff[HDIM * 4];      // packed (d-pairs) 0.5*scale[h]*M[h][:]
__device__ float  g_c2[DDIM];

// ------------------------- fold: Out[H,8] = A[H,H] @ B[H,8] ----------------
// warp-per-row; lane-parallel K; shfl tree reduction. mode selects B/Out:
//   0: B=Bext(Wp) -> g_R1   1: B=g_R1 -> g_R2   2: B=g_R2 -> g_M
__global__ void __launch_bounds__(256) fold_kernel(const float* __restrict__ A,
                                                   const float* __restrict__ Bext,
                                                   int mode) {
    __shared__ u64 Bs[HDIM * 4];
    const u64* Bv = (mode == 0) ? (const u64*)Bext
                   : (mode == 1) ? (const u64*)g_R1 : (const u64*)g_R2;
    float* Out = (mode == 0) ? g_R1 : (mode == 1) ? g_R2 : g_M;
    int t = threadIdx.x;
    for (int i = t; i < HDIM * 4; i += 256) Bs[i] = Bv[i];
    __syncthreads();

    int h = blockIdx.x * 8 + (t >> 5);
    int lane = t & 31;
    const float* Ar = A + h * HDIM;
    u64 a0 = 0, a1 = 0, a2 = 0, a3 = 0;
#pragma unroll
    for (int i = 0; i < 8; i++) {
        int k = lane + 32 * i;
        float a = __ldg(Ar + k);
        u64 aa = pk(a, a);
        a0 = f2fma(aa, Bs[k * 4 + 0], a0);
        a1 = f2fma(aa, Bs[k * 4 + 1], a1);
        a2 = f2fma(aa, Bs[k * 4 + 2], a2);
        a3 = f2fma(aa, Bs[k * 4 + 3], a3);
    }
    float r[8];
    upk(a0, r[0], r[1]); upk(a1, r[2], r[3]);
    upk(a2, r[4], r[5]); upk(a3, r[6], r[7]);
#pragma unroll
    for (int off = 16; off; off >>= 1)
#pragma unroll
        for (int d = 0; d < 8; d++) r[d] += __shfl_xor_sync(0xffffffffu, r[d], off);
    if (lane == 0) {
        float4* o = (float4*)(Out + h * 8);
        o[0] = make_float4(r[0], r[1], r[2], r[3]);
        o[1] = make_float4(r[4], r[5], r[6], r[7]);
    }
}

// ------------------------- pass A: BN statistics of h1 ---------------------
// thread = channel; W1 column resident in packed registers; nc staged in smem.
__global__ void __launch_bounds__(256) stats_kernel(const float* __restrict__ nf,
                                                    const int* __restrict__ ei0,
                                                    const int* __restrict__ ei1,
                                                    const float* __restrict__ W1,
                                                    const float* __restrict__ b1,
                                                    int E) {
    __shared__ u64 ncs[256 * 4];
    int t = threadIdx.x;
    u64 w0 = pk(0.5f * W1[0 * HDIM + t], 0.5f * W1[1 * HDIM + t]);
    u64 w1 = pk(0.5f * W1[2 * HDIM + t], 0.5f * W1[3 * HDIM + t]);
    u64 w2 = pk(0.5f * W1[4 * HDIM + t], 0.5f * W1[5 * HDIM + t]);
    u64 w3 = pk(0.5f * W1[6 * HDIM + t], 0.5f * W1[7 * HDIM + t]);
    float b1h = b1[t];
    float sum = 0.f, sq = 0.f;
    const float4* nfp = (const float4*)nf;

    for (int base = blockIdx.x * 256; base < E; base += gridDim.x * 256) {
        int nval = min(256, E - base);
        __syncthreads();
        if (t < nval) {
            int e = base + t;
            int s = __ldg(ei0 + e), g = __ldg(ei1 + e);
            float4 a0 = __ldg(nfp + 2 * s), a1 = __ldg(nfp + 2 * s + 1);
            float4 c0 = __ldg(nfp + 2 * g), c1 = __ldg(nfp + 2 * g + 1);
            ncs[t * 4 + 0] = pk(a0.x + c0.x, a0.y + c0.y);
            ncs[t * 4 + 1] = pk(a0.z + c0.z, a0.w + c0.w);
            ncs[t * 4 + 2] = pk(a1.x + c1.x, a1.y + c1.y);
            ncs[t * 4 + 3] = pk(a1.z + c1.z, a1.w + c1.w);
        }
        __syncthreads();
#pragma unroll 4
        for (int j = 0; j < nval; j++) {
            u64 s_ = f2mul(ncs[j * 4 + 0], w0);
            s_ = f2fma(ncs[j * 4 + 1], w1, s_);
            s_ = f2fma(ncs[j * 4 + 2], w2, s_);
            s_ = f2fma(ncs[j * 4 + 3], w3, s_);
            float lo, hi; upk(s_, lo, hi);
            float h1 = fmaxf(lo + hi + b1h, 0.f);
            sum += h1;
            sq = fmaf(h1, h1, sq);
        }
    }
    g_ps[blockIdx.x * HDIM + t] = make_float2(sum, sq);
}

// ------------------------- reduce + finalize + bias chain ------------------
__global__ void __launch_bounds__(256) finalize_kernel(const float* __restrict__ gamma,
                                                       const float* __restrict__ beta,
                                                       const float* __restrict__ b2,
                                                       const float* __restrict__ bv,
                                                       const float* __restrict__ bo,
                                                       const float* __restrict__ bp,
                                                       const float* __restrict__ Wp,
                                                       int E) {
    __shared__ float vsh[HDIM * 9];   // padded: stride 9 avoids bank conflicts
    int t = threadIdx.x;
    float s = 0.f, q = 0.f;
#pragma unroll 8
    for (int b = 0; b < NBLKA; b++) {
        float2 p = g_ps[b * HDIM + t];
        s += p.x; q += p.y;
    }
    float invE = 1.0f / (float)E;
    float mu = s * invE;
    float var = fmaxf(q * invE - mu * mu, 0.f);
    float scl = gamma[t] * rsqrtf(var + 1e-5f);
    float shf = beta[t] - mu * scl;

    float b2t = b2[t], bvt = bv[t], bot = bo[t];
#pragma unroll
    for (int d = 0; d < DDIM; d++) {
        float m = g_M[t * 8 + d];
        vsh[t * 9 + d] = shf * m + b2t * g_R2[t * 8 + d]
                       + bvt * g_R1[t * 8 + d] + bot * __ldg(Wp + t * 8 + d);
    }
#pragma unroll
    for (int p = 0; p < 4; p++)
        g_Meff[t * 4 + p] = pk(0.5f * scl * g_M[t * 8 + 2 * p],
                               0.5f * scl * g_M[t * 8 + 2 * p + 1]);
    __syncthreads();

    int w = t >> 5, lane = t & 31;
    if (w < DDIM) {
        float r = 0.f;
#pragma unroll
        for (int i = 0; i < 8; i++) r += vsh[(lane + 32 * i) * 9 + w];
#pragma unroll
        for (int off = 16; off; off >>= 1) r += __shfl_xor_sync(0xffffffffu, r, off);
        if (lane == 0) g_c2[w] = 0.5f * (bp[w] + r);
    }
}

// ------------------------- pass B: main (4 edges / thread) -----------------
__global__ void __launch_bounds__(256, 2) main_kernel(const float* __restrict__ edge_attr,
                                                      const float* __restrict__ nf,
                                                      const int* __restrict__ ei0,
                                                      const int* __restrict__ ei1,
                                                      const float* __restrict__ W1,
                                                      const float* __restrict__ b1,
                                                      float* __restrict__ out,
                                                      int E) {
    __shared__ u64 wp[HDIM * 4];
    __shared__ u64 mp[HDIM * 4];
    __shared__ float b1s[HDIM];
    int t = threadIdx.x;
    for (int idx = t; idx < HDIM * 4; idx += 256) {
        int h = idx >> 2, p = idx & 3;
        wp[idx] = pk(0.5f * W1[(2 * p) * HDIM + h], 0.5f * W1[(2 * p + 1) * HDIM + h]);
        mp[idx] = g_Meff[idx];
    }
    b1s[t] = b1[t];
    __syncthreads();

    int base = (blockIdx.x * 256 + t) * 4;
    if (base >= E) return;

    int ee[4];
#pragma unroll
    for (int i = 0; i < 4; i++) ee[i] = min(base + i, E - 1);

    const float4* nfp = (const float4*)nf;
    u64 n[4][4];
#pragma unroll
    for (int i = 0; i < 4; i++) {
        int s = __ldg(ei0 + ee[i]), g = __ldg(ei1 + ee[i]);
        float4 a0 = __ldg(nfp + 2 * s), a1 = __ldg(nfp + 2 * s + 1);
        float4 c0 = __ldg(nfp + 2 * g), c1 = __ldg(nfp + 2 * g + 1);
        n[i][0] = pk(a0.x + c0.x, a0.y + c0.y);
        n[i][1] = pk(a0.z + c0.z, a0.w + c0.w);
        n[i][2] = pk(a1.x + c1.x, a1.y + c1.y);
        n[i][3] = pk(a1.z + c1.z, a1.w + c1.w);
    }

    u64 acc[4][4];
#pragma unroll
    for (int i = 0; i < 4; i++)
#pragma unroll
        for (int p = 0; p < 4; p++) acc[i][p] = 0;

#pragma unroll 2
    for (int h = 0; h < HDIM; h++) {
        u64 w0 = wp[h * 4 + 0], w1 = wp[h * 4 + 1], w2 = wp[h * 4 + 2], w3 = wp[h * 4 + 3];
        u64 m0 = mp[h * 4 + 0], m1 = mp[h * 4 + 1], m2 = mp[h * 4 + 2], m3 = mp[h * 4 + 3];
        float bb = b1s[h];
#pragma unroll
        for (int i = 0; i < 4; i++) {
            u64 s_ = f2mul(n[i][0], w0);
            s_ = f2fma(n[i][1], w1, s_);
            s_ = f2fma(n[i][2], w2, s_);
            s_ = f2fma(n[i][3], w3, s_);
            float lo, hi; upk(s_, lo, hi);
            float h1 = fmaxf(lo + hi + bb, 0.f);
            u64 hh = pk(h1, h1);
            acc[i][0] = f2fma(hh, m0, acc[i][0]);
            acc[i][1] = f2fma(hh, m1, acc[i][1]);
            acc[i][2] = f2fma(hh, m2, acc[i][2]);
            acc[i][3] = f2fma(hh, m3, acc[i][3]);
        }
    }

    float cz[8];
#pragma unroll
    for (int d = 0; d < 8; d++) cz[d] = g_c2[d];

    const float4* eap = (const float4*)edge_attr;
    float4* outp = (float4*)out;
#pragma unroll
    for (int i = 0; i < 4; i++) {
        int e = base + i;
        if (e >= E) break;
        float4 e0 = __ldg(eap + e * 2), e1 = __ldg(eap + e * 2 + 1);
        float x0, x1, x2, x3, x4, x5, x6, x7;
        upk(acc[i][0], x0, x1); upk(acc[i][1], x2, x3);
        upk(acc[i][2], x4, x5); upk(acc[i][3], x6, x7);
        float4 o0, o1;
        o0.x = e0.x + x0 + cz[0]; o0.y = e0.y + x1 + cz[1];
        o0.z = e0.z + x2 + cz[2]; o0.w = e0.w + x3 + cz[3];
        o1.x = e1.x + x4 + cz[4]; o1.y = e1.y + x5 + cz[5];
        o1.z = e1.z + x6 + cz[6]; o1.w = e1.w + x7 + cz[7];
        outp[e * 2] = o0; outp[e * 2 + 1] = o1;
    }
}

// ------------------------- launch ------------------------------------------
extern "C" void kernel_launch(void* const* d_in, const int* in_sizes, int n_in,
                              void* d_out, int out_size) {
    const float* edge_attr = (const float*)d_in[0];
    const float* nf        = (const float*)d_in[1];
    const int*   ei        = (const int*)  d_in[2];
    // d_in[3..8] = edge encoder params: dead code in the reference, unused.
    const float* nW1   = (const float*)d_in[9];
    const float* nb1   = (const float*)d_in[10];
    const float* ngam  = (const float*)d_in[11];
    const float* nbet  = (const float*)d_in[12];
    const float* nW2   = (const float*)d_in[13];
    const float* nb2   = (const float*)d_in[14];
    const float* Wv    = (const float*)d_in[15];
    const float* bv    = (const float*)d_in[16];
    const float* Wo    = (const float*)d_in[17];
    const float* bo    = (const float*)d_in[18];
    const float* Wp    = (const float*)d_in[19];
    const float* bp    = (const float*)d_in[20];
    (void)n_in; (void)out_size;

    int E = in_sizes[0] / DDIM;
    const int* ei0 = ei;
    const int* ei1 = ei + E;
    float* out = (float*)d_out;

    // BN statistics first (longest independent chain starts immediately)
    stats_kernel<<<NBLKA, 256>>>(nf, ei0, ei1, nW1, nb1, E);

    // weight folding (tiny, warp-parallel)
    fold_kernel<<<32, 256>>>(Wo, Wp, 0);    // R1 = Wo @ Wp
    fold_kernel<<<32, 256>>>(Wv, Wp, 1);    // R2 = Wv @ R1
    fold_kernel<<<32, 256>>>(nW2, Wp, 2);   // M  = nW2 @ R2

    finalize_kernel<<<1, 256>>>(ngam, nbet, nb2, bv, bo, bp, Wp, E);

    // main fused pass, 4 edges / thread
    int gridB = (E + 1023) / 1024;
    main_kernel<<<gridB, 256>>>(edge_attr, nf, ei0, ei1, nW1, nb1, out, E);
}